// round 15
// baseline (speedup 1.0000x reference)
#include <cuda_runtime.h>
#include <cuda_fp16.h>
#include <cstdint>
#include <math.h>

// Problem constants
constexpr int B = 2;
constexpr int H = 16;
constexpr int N = 2048;
constexpr int A = 128;           // head dim
constexpr int W = 2048;          // model width
constexpr int HD = H * A;        // 2048
constexpr int Mdim = B * N;      // 4096
constexpr int Kdim = W;          // 2048

// Scratch (device globals — no allocation allowed). All fp16.
__device__ __half g_qh [Mdim * Kdim];
__device__ __half g_Wqh[HD * W];
__device__ __half g_Wkh[HD * W];
__device__ __half g_Wvh[HD * W];
__device__ __half g_Woh[W * HD];
__device__ __half g_Qh [B * H * N * A];   // head-major, rope+scale*log2e applied
__device__ __half g_Kh [B * H * N * A];   // head-major, rope applied
__device__ __half g_VTh[B * H * A * N];   // TRANSPOSED: [b][h][d][n]
__device__ __half g_AOh[Mdim * HD];       // [b*n, h*a]
__device__ float2 g_rope[N * 64];         // (sin, cos) per (n, pair)

// ---------------------------------------------------------------------------
// helpers
// ---------------------------------------------------------------------------
__device__ __forceinline__ float ex2f(float x) {
    float y;
    asm("ex2.approx.ftz.f32 %0, %1;" : "=f"(y) : "f"(x));
    return y;
}
__device__ __forceinline__ uint32_t pack_f16x2(float lo, float hi) {
    uint32_t r;
    asm("cvt.rn.f16x2.f32 %0, %1, %2;" : "=r"(r) : "f"(hi), "f"(lo));
    return r;
}
__device__ __forceinline__ uint32_t smem_u32(const void* p) {
    uint32_t a;
    asm("{ .reg .u64 t; cvta.to.shared.u64 t, %1; cvt.u32.u64 %0, t; }"
        : "=r"(a) : "l"(p));
    return a;
}
__device__ __forceinline__ void mma_f16(float* c, const uint32_t* a,
                                        uint32_t b0, uint32_t b1) {
    asm volatile(
        "mma.sync.aligned.m16n8k16.row.col.f32.f16.f16.f32 "
        "{%0,%1,%2,%3}, {%4,%5,%6,%7}, {%8,%9}, {%0,%1,%2,%3};"
        : "+f"(c[0]), "+f"(c[1]), "+f"(c[2]), "+f"(c[3])
        : "r"(a[0]), "r"(a[1]), "r"(a[2]), "r"(a[3]), "r"(b0), "r"(b1));
}
__device__ __forceinline__ void ldsm_x4(uint32_t* r, uint32_t addr) {
    asm volatile("ldmatrix.sync.aligned.m8n8.x4.shared.b16 {%0,%1,%2,%3}, [%4];"
                 : "=r"(r[0]), "=r"(r[1]), "=r"(r[2]), "=r"(r[3]) : "r"(addr));
}
#define CP_ASYNC16(dst, src) \
    asm volatile("cp.async.cg.shared.global [%0], [%1], 16;" :: "r"(dst), "l"(src))
#define CP_COMMIT() asm volatile("cp.async.commit_group;" ::: "memory")
#define CP_WAIT(n)  asm volatile("cp.async.wait_group %0;" :: "n"(n) : "memory")

// ---------------------------------------------------------------------------
// rope sin/cos table: theta[n, i] = n * 10000^{-i/63}
// ---------------------------------------------------------------------------
__global__ void rope_table_kernel() {
    int idx = blockIdx.x * blockDim.x + threadIdx.x;   // [0, 2048*64)
    int i = idx & 63, n = idx >> 6;
    float freq = __powf(10000.0f, -(float)i * (1.0f / 63.0f));
    float s, c;
    sincosf((float)n * freq, &s, &c);
    g_rope[idx] = make_float2(s, c);
}

// ---------------------------------------------------------------------------
// fp32 -> fp16 conversion pre-pass over q + 4 weights (single launch).
// ---------------------------------------------------------------------------
constexpr int NQ4 = Mdim * Kdim / 4;   // 2,097,152
constexpr int NW4 = HD * W / 4;        // 1,048,576 = 2^20

__global__ void cvt_all_kernel(const float4* __restrict__ q,
                               const float4* __restrict__ wq,
                               const float4* __restrict__ wk,
                               const float4* __restrict__ wv,
                               const float4* __restrict__ wo,
                               __half* __restrict__ qh,
                               __half* __restrict__ wqh,
                               __half* __restrict__ wkh,
                               __half* __restrict__ wvh,
                               __half* __restrict__ woh) {
    int i = blockIdx.x * blockDim.x + threadIdx.x;
    const float4* src;
    __half* dst;
    int off;
    if (i < NQ4) {
        src = q; dst = qh; off = i;
    } else {
        int j = i - NQ4;
        int w = j >> 20;
        off = j & (NW4 - 1);
        src = (w == 0) ? wq : (w == 1) ? wk : (w == 2) ? wv : wo;
        dst = (w == 0) ? wqh : (w == 1) ? wkh : (w == 2) ? wvh : woh;
    }
    float4 v = src[off];
    uint2 p = make_uint2(pack_f16x2(v.x, v.y), pack_f16x2(v.z, v.w));
    *(uint2*)(dst + (size_t)off * 4) = p;
}

// ---------------------------------------------------------------------------
// fp16 mma.sync GEMM v3: C[M,Nc] = A[M,K] @ B[Nc,K]^T, m16n8k16.
// CTA tile 128x256, BK=64, 256 threads, 8 warps of 64x64 (2m x 4n),
// 3-stage cp.async (144KB smem, 1 CTA/SM, 8 warps/SM),
// XOR-swizzled 128B rows, ldmatrix.x4.
// L1 bytes per MAC: 88KB/1M (-31% vs 128x128 variants).
// OUTMODE: 0 = fp32 row-major; 1 = fp16 head-major (rope+prescale);
//          2 = fp16 head-major transposed ([b][h][d][n]).
// ---------------------------------------------------------------------------
constexpr int GTILE_A    = 128 * 128;             // 16384 B
constexpr int GTILE_B2   = 256 * 128;             // 32768 B
constexpr int GSTAGE_B   = GTILE_A + GTILE_B2;    // 49152
constexpr int GEMM_SMEM  = 3 * GSTAGE_B;          // 147456

template <int OUTMODE>
__device__ __forceinline__ void gemm_body(const __half* __restrict__ Ag,
                                          const __half* __restrict__ Bg,
                                          void* __restrict__ Cg,
                                          bool doRope, float prescale) {
    extern __shared__ char gsc[];
    const uint32_t sbase = smem_u32(gsc);
    const int tid  = threadIdx.x;
    const int lane = tid & 31;
    const int wid  = tid >> 5;      // 0..7
    const int wm   = wid & 1;       // 64 rows each
    const int wn   = wid >> 1;      // 64 cols each (0..3)
    const int m0   = blockIdx.y * 128;
    const int n0   = blockIdx.x * 256;

    float c[4][8][4];
#pragma unroll
    for (int mi = 0; mi < 4; mi++)
#pragma unroll
        for (int ni = 0; ni < 8; ni++)
#pragma unroll
            for (int j = 0; j < 4; j++) c[mi][ni][j] = 0.f;

    // staging: A 1024 chunks + B 2048 chunks of 16B, 12 per thread
    auto stage = [&](int kt, int slot) {
        const uint32_t base = sbase + slot * GSTAGE_B;
#pragma unroll
        for (int i = 0; i < 4; i++) {
            int cidx = tid + i * 256;
            int row = cidx >> 3, ch = cidx & 7;
            uint32_t off = (uint32_t)row * 128 + ((ch ^ (row & 7)) << 4);
            CP_ASYNC16(base + off,
                       Ag + (size_t)(m0 + row) * Kdim + kt * 64 + ch * 8);
        }
#pragma unroll
        for (int i = 0; i < 8; i++) {
            int cidx = tid + i * 256;
            int row = cidx >> 3, ch = cidx & 7;
            uint32_t off = (uint32_t)row * 128 + ((ch ^ (row & 7)) << 4);
            CP_ASYNC16(base + GTILE_A + off,
                       Bg + (size_t)(n0 + row) * Kdim + kt * 64 + ch * 8);
        }
    };

    const int a_row = wm * 64 + (lane & 15);
    const int a_hi  = lane >> 4;
    const int b_row = wn * 64 + (lane & 7) + ((lane >> 4) << 3);
    const int b_hi  = (lane >> 3) & 1;

    stage(0, 0); CP_COMMIT();
    stage(1, 1); CP_COMMIT();

    constexpr int NKT = Kdim / 64;   // 32
    int slot = 0;
    for (int kt = 0; kt < NKT; kt++) {
        CP_WAIT(1);
        __syncthreads();
        if (kt + 2 < NKT) {
            int ns = slot + 2; if (ns >= 3) ns -= 3;
            stage(kt + 2, ns);
        }
        CP_COMMIT();

        const uint32_t abase = sbase + slot * GSTAGE_B;
        const uint32_t bbase = abase + GTILE_A;
#pragma unroll
        for (int ks = 0; ks < 4; ks++) {   // k16 steps
            uint32_t af[4][4];
#pragma unroll
            for (int mi = 0; mi < 4; mi++) {
                int row = a_row + mi * 16;
                uint32_t addr = abase + (uint32_t)row * 128
                              + (((ks * 2 + a_hi) ^ (row & 7)) << 4);
                ldsm_x4(af[mi], addr);
            }
#pragma unroll
            for (int nip = 0; nip < 4; nip++) {
                int row = b_row + nip * 16;
                uint32_t addr = bbase + (uint32_t)row * 128
                              + (((ks * 2 + b_hi) ^ (row & 7)) << 4);
                uint32_t bf[4];
                ldsm_x4(bf, addr);
#pragma unroll
                for (int mi = 0; mi < 4; mi++) {
                    mma_f16(c[mi][2 * nip],     af[mi], bf[0], bf[1]);
                    mma_f16(c[mi][2 * nip + 1], af[mi], bf[2], bf[3]);
                }
            }
        }
        slot++; if (slot >= 3) slot = 0;
    }

    const int gid = lane >> 2, tig = lane & 3;
#pragma unroll
    for (int mi = 0; mi < 4; mi++) {
#pragma unroll
        for (int ni = 0; ni < 8; ni++) {
            int n = n0 + wn * 64 + ni * 8 + tig * 2;
#pragma unroll
            for (int half2i = 0; half2i < 2; half2i++) {
                int m = m0 + wm * 64 + mi * 16 + gid + half2i * 8;
                float2 v = make_float2(c[mi][ni][half2i * 2],
                                       c[mi][ni][half2i * 2 + 1]);
                if (OUTMODE == 0) {
                    *(float2*)((float*)Cg + (size_t)m * 2048 + n) = v;
                } else {
                    if (doRope) {
                        int pi   = (n & 127) >> 1;
                        int npos = m & 2047;
                        float2 sc = g_rope[(npos << 6) + pi];
                        float ev = v.x * sc.y - v.y * sc.x;
                        float ov = v.y * sc.y + v.x * sc.x;
                        v = make_float2(ev, ov);
                    }
                    v.x *= prescale; v.y *= prescale;
                    int b2 = m >> 11, np = m & 2047, h2 = n >> 7, a0 = n & 127;
                    if (OUTMODE == 2) {
                        __half* p = (__half*)Cg
                                  + (((size_t)b2 * H + h2) * A + a0) * N + np;
                        p[0] = __float2half_rn(v.x);
                        p[N] = __float2half_rn(v.y);
                    } else {
                        uint32_t pk = pack_f16x2(v.x, v.y);
                        *(uint32_t*)((__half*)Cg
                            + ((((size_t)b2 * H + h2) * N) + np) * A + a0) = pk;
                    }
                }
            }
        }
    }
}

// Q/K/V fused projections. z=0: Q (rope + scale*log2e), z=1: K (rope),
// z=2: V (transposed store).
__global__ __launch_bounds__(256, 1)
void qkv_gemm(const __half* __restrict__ q,
              const __half* __restrict__ Wq, const __half* __restrict__ Wk,
              const __half* __restrict__ Wv,
              __half* __restrict__ Qp, __half* __restrict__ Kp,
              __half* __restrict__ VTp) {
    const int z = blockIdx.z;
    const float QSCL = 0.08838834764831845f * 1.4426950408889634f;
    if (z == 0)      gemm_body<1>(q, Wq, Qp,  true,  QSCL);
    else if (z == 1) gemm_body<1>(q, Wk, Kp,  true,  1.0f);
    else             gemm_body<2>(q, Wv, VTp, false, 1.0f);
}

__global__ __launch_bounds__(256, 1)
void out_gemm(const __half* __restrict__ Ag, const __half* __restrict__ Bg,
              float* __restrict__ Cg) {
    gemm_body<0>(Ag, Bg, Cg, false, 1.0f);
}

// ---------------------------------------------------------------------------
// fp16 tensor-core causal flash attention (unchanged from R13/R14).
// CTA: 64 queries, 128 threads (4 warps x 16 q rows), 64-key tiles, 3-stage.
// ---------------------------------------------------------------------------
constexpr int AQT = 64;
constexpr int AKT = 64;
constexpr int K_TILE_B   = AKT * 256;              // 16384 (64 rows x 256B)
constexpr int V_TILE_B   = 128 * 128;              // 16384 (128 rows x 128B)
constexpr int ASTAGE_B   = K_TILE_B + V_TILE_B;    // 32768
constexpr int ATTN_SMEM  = 3 * ASTAGE_B;           // 98304

__global__ __launch_bounds__(128, 2)
void attn_mma_kernel(const __half* __restrict__ Q, const __half* __restrict__ K,
                     const __half* __restrict__ VT, __half* __restrict__ O) {
    extern __shared__ char smc[];
    const uint32_t sbase = smem_u32(smc);

    const int tid  = threadIdx.x;
    const int lane = tid & 31;
    const int wid  = tid >> 5;          // 0..3
    const int gid  = lane >> 2, tig = lane & 3;
    const int bh   = blockIdx.y;
    const int qt   = gridDim.x - 1 - blockIdx.x;   // heavy tiles first
    const int q0   = qt * AQT;

    const __half* Qb  = Q  + (size_t)bh * N * A;
    const __half* Kb  = K  + (size_t)bh * N * A;
    const __half* VTb = VT + (size_t)bh * A * N;

    // ---- stage Q (64 rows x 256B) into stage-0 alias ----
    {
#pragma unroll
        for (int i = 0; i < 8; i++) {
            int cidx = tid + i * 128;          // 0..1023
            int row = cidx >> 4, ch = cidx & 15;
            uint32_t off = (uint32_t)row * 256 + ((ch ^ (row & 7)) << 4);
            CP_ASYNC16(sbase + off, Qb + (size_t)(q0 + row) * A + ch * 8);
        }
        CP_COMMIT();
        CP_WAIT(0);
        __syncthreads();
    }

    // ---- Q A-frags -> registers (already scaled in projection) ----
    uint32_t qf[8][4];
    {
        const int a_row = wid * 16 + (lane & 15);
        const int a_hi  = lane >> 4;
#pragma unroll
        for (int kd = 0; kd < 8; kd++) {
            uint32_t addr = sbase + (uint32_t)a_row * 256
                          + (((kd * 2 + a_hi) ^ (a_row & 7)) << 4);
            ldsm_x4(qf[kd], addr);
        }
    }
    __syncthreads();   // Q smem now reusable as KV stage 0

    // ---- KV staging ----
    auto stage = [&](int kt, int slot) {
        const uint32_t kb = sbase + slot * ASTAGE_B;
        const uint32_t vb = kb + K_TILE_B;
        const __half* Kg  = Kb  + (size_t)(kt * AKT) * A;
        const __half* VTg = VTb + (size_t)(kt * AKT);
#pragma unroll
        for (int i = 0; i < 8; i++) {
            int cidx = tid + i * 128;
            int row = cidx >> 4, ch = cidx & 15;
            uint32_t off = (uint32_t)row * 256 + ((ch ^ (row & 7)) << 4);
            CP_ASYNC16(kb + off, Kg + (size_t)row * A + ch * 8);
        }
#pragma unroll
        for (int i = 0; i < 8; i++) {
            int cidx = tid + i * 128;
            int row = cidx >> 3, ch = cidx & 7;   // d row, key chunk
            uint32_t off = (uint32_t)row * 128 + ((ch ^ (row & 7)) << 4);
            CP_ASYNC16(vb + off, VTg + (size_t)row * N + ch * 8);
        }
    };

    const int nkt = qt + 1;

    float o[16][4];
#pragma unroll
    for (int nf = 0; nf < 16; nf++)
#pragma unroll
        for (int j = 0; j < 4; j++) o[nf][j] = 0.f;
    float m0 = -1e30f, m1 = -1e30f, l0 = 0.f, l1 = 0.f;

    const int row0 = q0 + wid * 16 + gid;
    const int row1 = row0 + 8;
    const int b_row = (lane & 7) + ((lane >> 4) << 3);   // 0..15
    const int b_hi  = (lane >> 3) & 1;

    stage(0, 0); CP_COMMIT();
    if (nkt > 1) { stage(1, 1); } CP_COMMIT();

    int slot = 0;
    for (int kt = 0; kt < nkt; kt++) {
        CP_WAIT(1);
        __syncthreads();
        if (kt + 2 < nkt) {
            int ns = slot + 2; if (ns >= 3) ns -= 3;
            stage(kt + 2, ns);
        }
        CP_COMMIT();

        const uint32_t kbase = sbase + slot * ASTAGE_B;
        const uint32_t vbase = kbase + K_TILE_B;

        // ---- S = Q K^T (64 keys = 8 n-groups) ----
        float s[8][4];
#pragma unroll
        for (int nk = 0; nk < 8; nk++)
#pragma unroll
            for (int j = 0; j < 4; j++) s[nk][j] = 0.f;

#pragma unroll
        for (int kd = 0; kd < 8; kd++) {
#pragma unroll
            for (int g = 0; g < 4; g++) {
                int row = b_row + g * 16;
                uint32_t addr = kbase + (uint32_t)row * 256
                              + (((kd * 2 + b_hi) ^ (row & 7)) << 4);
                uint32_t bf[4];
                ldsm_x4(bf, addr);
                mma_f16(s[2 * g],     qf[kd], bf[0], bf[1]);
                mma_f16(s[2 * g + 1], qf[kd], bf[2], bf[3]);
            }
        }

        // ---- causal mask (diagonal tile only) ----
        if (kt == nkt - 1) {
            int colb = kt * AKT + 2 * tig;
#pragma unroll
            for (int nk = 0; nk < 8; nk++) {
                int c0 = colb + nk * 8;
                if (c0     > row0) s[nk][0] = -1e30f;
                if (c0 + 1 > row0) s[nk][1] = -1e30f;
                if (c0     > row1) s[nk][2] = -1e30f;
                if (c0 + 1 > row1) s[nk][3] = -1e30f;
            }
        }

        // ---- online softmax (log2 domain) ----
        float mx0 = -1e30f, mx1 = -1e30f;
#pragma unroll
        for (int nk = 0; nk < 8; nk++) {
            mx0 = fmaxf(mx0, fmaxf(s[nk][0], s[nk][1]));
            mx1 = fmaxf(mx1, fmaxf(s[nk][2], s[nk][3]));
        }
        mx0 = fmaxf(mx0, __shfl_xor_sync(0xffffffffu, mx0, 1));
        mx0 = fmaxf(mx0, __shfl_xor_sync(0xffffffffu, mx0, 2));
        mx1 = fmaxf(mx1, __shfl_xor_sync(0xffffffffu, mx1, 1));
        mx1 = fmaxf(mx1, __shfl_xor_sync(0xffffffffu, mx1, 2));
        float mn0 = fmaxf(m0, mx0), mn1 = fmaxf(m1, mx1);
        float cor0 = ex2f(m0 - mn0), cor1 = ex2f(m1 - mn1);
        m0 = mn0; m1 = mn1;

        float rs0 = 0.f, rs1 = 0.f;
#pragma unroll
        for (int nk = 0; nk < 8; nk++) {
            s[nk][0] = ex2f(s[nk][0] - mn0);
            s[nk][1] = ex2f(s[nk][1] - mn0);
            s[nk][2] = ex2f(s[nk][2] - mn1);
            s[nk][3] = ex2f(s[nk][3] - mn1);
            rs0 += s[nk][0] + s[nk][1];
            rs1 += s[nk][2] + s[nk][3];
        }
        rs0 += __shfl_xor_sync(0xffffffffu, rs0, 1);
        rs0 += __shfl_xor_sync(0xffffffffu, rs0, 2);
        rs1 += __shfl_xor_sync(0xffffffffu, rs1, 1);
        rs1 += __shfl_xor_sync(0xffffffffu, rs1, 2);
        l0 = l0 * cor0 + rs0;
        l1 = l1 * cor1 + rs1;

#pragma unroll
        for (int nf = 0; nf < 16; nf++) {
            o[nf][0] *= cor0; o[nf][1] *= cor0;
            o[nf][2] *= cor1; o[nf][3] *= cor1;
        }

        // ---- P A-frags: fp16x2 packs of S C-frags (no transpose needed) ----
        uint32_t aP[4][4];
#pragma unroll
        for (int kf = 0; kf < 4; kf++) {
            aP[kf][0] = pack_f16x2(s[2 * kf][0],     s[2 * kf][1]);
            aP[kf][1] = pack_f16x2(s[2 * kf][2],     s[2 * kf][3]);
            aP[kf][2] = pack_f16x2(s[2 * kf + 1][0], s[2 * kf + 1][1]);
            aP[kf][3] = pack_f16x2(s[2 * kf + 1][2], s[2 * kf + 1][3]);
        }

        // ---- O += P V : ldmatrix B-frags from d-major Vt tile ----
#pragma unroll
        for (int kf = 0; kf < 4; kf++) {
#pragma unroll
            for (int dp = 0; dp < 8; dp++) {
                int row = dp * 16 + b_row;   // d row 0..127
                uint32_t addr = vbase + (uint32_t)row * 128
                              + (((kf * 2 + b_hi) ^ (row & 7)) << 4);
                uint32_t bf[4];
                ldsm_x4(bf, addr);
                mma_f16(o[2 * dp],     aP[kf], bf[0], bf[1]);
                mma_f16(o[2 * dp + 1], aP[kf], bf[2], bf[3]);
            }
        }

        slot++; if (slot >= 3) slot = 0;
    }

    // ---- write output: fp16 [b*n, h*a] ----
    const float il0 = 1.f / l0, il1 = 1.f / l1;
    const int b2 = bh >> 4, h2 = bh & 15;
    __half* o0 = O + (size_t)(b2 * N + row0) * HD + h2 * A;
    __half* o1 = O + (size_t)(b2 * N + row1) * HD + h2 * A;
#pragma unroll
    for (int nf = 0; nf < 16; nf++) {
        int col = nf * 8 + 2 * tig;
        *(uint32_t*)(o0 + col) = pack_f16x2(o[nf][0] * il0, o[nf][1] * il0);
        *(uint32_t*)(o1 + col) = pack_f16x2(o[nf][2] * il1, o[nf][3] * il1);
    }
}

// ---------------------------------------------------------------------------
extern "C" void kernel_launch(void* const* d_in, const int* in_sizes, int n_in,
                              void* d_out, int out_size) {
    const float* q  = (const float*)d_in[0];
    const float* Wq = (const float*)d_in[1];
    const float* Wk = (const float*)d_in[2];
    const float* Wv = (const float*)d_in[3];
    const float* Wo = (const float*)d_in[4];
    float* out = (float*)d_out;

    __half *qh, *Wqh, *Wkh, *Wvh, *Woh, *Qh, *Kh, *VTh, *AOh;
    cudaGetSymbolAddress((void**)&qh,  g_qh);
    cudaGetSymbolAddress((void**)&Wqh, g_Wqh);
    cudaGetSymbolAddress((void**)&Wkh, g_Wkh);
    cudaGetSymbolAddress((void**)&Wvh, g_Wvh);
    cudaGetSymbolAddress((void**)&Woh, g_Woh);
    cudaGetSymbolAddress((void**)&Qh,  g_Qh);
    cudaGetSymbolAddress((void**)&Kh,  g_Kh);
    cudaGetSymbolAddress((void**)&VTh, g_VTh);
    cudaGetSymbolAddress((void**)&AOh, g_AOh);

    cudaFuncSetAttribute(qkv_gemm, cudaFuncAttributeMaxDynamicSharedMemorySize,
                         GEMM_SMEM);
    cudaFuncSetAttribute(out_gemm, cudaFuncAttributeMaxDynamicSharedMemorySize,
                         GEMM_SMEM);
    cudaFuncSetAttribute(attn_mma_kernel,
                         cudaFuncAttributeMaxDynamicSharedMemorySize, ATTN_SMEM);

    // rope sin/cos table + fp16 conversion pre-pass (q + 4 weights)
    rope_table_kernel<<<(N * 64) / 256, 256>>>();
    {
        int total = NQ4 + 4 * NW4;   // 6,291,456
        cvt_all_kernel<<<total / 256, 256>>>(
            (const float4*)q, (const float4*)Wq, (const float4*)Wk,
            (const float4*)Wv, (const float4*)Wo,
            qh, Wqh, Wkh, Wvh, Woh);
    }

    // fused QKV projections (rope + scale fused; V stored transposed)
    qkv_gemm<<<dim3(HD / 256, Mdim / 128, 3), 256, GEMM_SMEM>>>(
        qh, Wqh, Wkh, Wvh, Qh, Kh, VTh);

    // fp16 tensor-core causal flash attention (64q CTAs, 64-key tiles)
    attn_mma_kernel<<<dim3(N / AQT, B * H), 128, ATTN_SMEM>>>(Qh, Kh, VTh, AOh);

    // output projection (fp32 result)
    out_gemm<<<dim3(W / 256, Mdim / 128), 256, GEMM_SMEM>>>(AOh, Woh, out);
}

// round 16
// speedup vs baseline: 1.1265x; 1.1265x over previous
#include <cuda_runtime.h>
#include <cuda_fp16.h>
#include <cstdint>
#include <math.h>

// Problem constants
constexpr int B = 2;
constexpr int H = 16;
constexpr int N = 2048;
constexpr int A = 128;           // head dim
constexpr int W = 2048;          // model width
constexpr int HD = H * A;        // 2048
constexpr int Mdim = B * N;      // 4096
constexpr int Kdim = W;          // 2048

// Scratch (device globals — no allocation allowed). All fp16.
__device__ __half g_qh [Mdim * Kdim];
__device__ __half g_Wqh[HD * W];
__device__ __half g_Wkh[HD * W];
__device__ __half g_Wvh[HD * W];
__device__ __half g_Woh[W * HD];
__device__ __half g_Qh [B * H * N * A];   // head-major, rope+scale*log2e applied
__device__ __half g_Kh [B * H * N * A];   // head-major, rope applied
__device__ __half g_VTh[B * H * A * N];   // TRANSPOSED: [b][h][d][n]
__device__ __half g_AOh[Mdim * HD];       // [b*n, h*a]
__device__ float2 g_rope[N * 64];         // (sin, cos) per (n, pair)

// ---------------------------------------------------------------------------
// helpers
// ---------------------------------------------------------------------------
__device__ __forceinline__ float ex2f(float x) {
    float y;
    asm("ex2.approx.ftz.f32 %0, %1;" : "=f"(y) : "f"(x));
    return y;
}
__device__ __forceinline__ uint32_t pack_f16x2(float lo, float hi) {
    uint32_t r;
    asm("cvt.rn.f16x2.f32 %0, %1, %2;" : "=r"(r) : "f"(hi), "f"(lo));
    return r;
}
__device__ __forceinline__ uint32_t smem_u32(const void* p) {
    uint32_t a;
    asm("{ .reg .u64 t; cvta.to.shared.u64 t, %1; cvt.u32.u64 %0, t; }"
        : "=r"(a) : "l"(p));
    return a;
}
__device__ __forceinline__ void mma_f16(float* c, const uint32_t* a,
                                        uint32_t b0, uint32_t b1) {
    asm volatile(
        "mma.sync.aligned.m16n8k16.row.col.f32.f16.f16.f32 "
        "{%0,%1,%2,%3}, {%4,%5,%6,%7}, {%8,%9}, {%0,%1,%2,%3};"
        : "+f"(c[0]), "+f"(c[1]), "+f"(c[2]), "+f"(c[3])
        : "r"(a[0]), "r"(a[1]), "r"(a[2]), "r"(a[3]), "r"(b0), "r"(b1));
}
__device__ __forceinline__ void ldsm_x4(uint32_t* r, uint32_t addr) {
    asm volatile("ldmatrix.sync.aligned.m8n8.x4.shared.b16 {%0,%1,%2,%3}, [%4];"
                 : "=r"(r[0]), "=r"(r[1]), "=r"(r[2]), "=r"(r[3]) : "r"(addr));
}
#define CP_ASYNC16(dst, src) \
    asm volatile("cp.async.cg.shared.global [%0], [%1], 16;" :: "r"(dst), "l"(src))
#define CP_COMMIT() asm volatile("cp.async.commit_group;" ::: "memory")
#define CP_WAIT(n)  asm volatile("cp.async.wait_group %0;" :: "n"(n) : "memory")

// ---------------------------------------------------------------------------
// Fused pre-pass: fp32->fp16 conversion of q + 4 weights, plus rope table.
// ---------------------------------------------------------------------------
constexpr int NQ4 = Mdim * Kdim / 4;   // 2,097,152
constexpr int NW4 = HD * W / 4;        // 1,048,576 = 2^20
constexpr int NTOT4 = NQ4 + 4 * NW4;   // 6,291,456
constexpr int NROPE = N * 64;          // 131,072

__global__ void cvt_all_kernel(const float4* __restrict__ q,
                               const float4* __restrict__ wq,
                               const float4* __restrict__ wk,
                               const float4* __restrict__ wv,
                               const float4* __restrict__ wo,
                               __half* __restrict__ qh,
                               __half* __restrict__ wqh,
                               __half* __restrict__ wkh,
                               __half* __restrict__ wvh,
                               __half* __restrict__ woh) {
    int i = blockIdx.x * blockDim.x + threadIdx.x;
    if (i >= NTOT4) {   // tail blocks: rope table
        int idx = i - NTOT4;
        if (idx < NROPE) {
            int pi = idx & 63, n = idx >> 6;
            float freq = __powf(10000.0f, -(float)pi * (1.0f / 63.0f));
            float s, c;
            sincosf((float)n * freq, &s, &c);
            g_rope[idx] = make_float2(s, c);
        }
        return;
    }
    const float4* src;
    __half* dst;
    int off;
    if (i < NQ4) {
        src = q; dst = qh; off = i;
    } else {
        int j = i - NQ4;
        int w = j >> 20;
        off = j & (NW4 - 1);
        src = (w == 0) ? wq : (w == 1) ? wk : (w == 2) ? wv : wo;
        dst = (w == 0) ? wqh : (w == 1) ? wkh : (w == 2) ? wvh : woh;
    }
    float4 v = src[off];
    uint2 p = make_uint2(pack_f16x2(v.x, v.y), pack_f16x2(v.z, v.w));
    *(uint2*)(dst + (size_t)off * 4) = p;
}

// ---------------------------------------------------------------------------
// fp16 mma.sync GEMM (R14 config — best measured): 128x128 CTA, BK=64,
// 256 threads, 8 warps of 64x32 (2m x 4n), 3-stage cp.async (96KB smem,
// 2 CTAs/SM), XOR-swizzled 128B rows, ldmatrix.x4.
// OUTMODE: 0 = fp32 row-major; 1 = fp16 head-major (rope+prescale);
//          2 = fp16 head-major transposed ([b][h][d][n]).
// ---------------------------------------------------------------------------
constexpr int GTILE_B    = 128 * 128;             // 16384 B per operand (fp16)
constexpr int GSTAGE_B   = 2 * GTILE_B;           // 32768
constexpr int GEMM_SMEM  = 3 * GSTAGE_B;          // 98304

template <int OUTMODE>
__device__ __forceinline__ void gemm_body(const __half* __restrict__ Ag,
                                          const __half* __restrict__ Bg,
                                          void* __restrict__ Cg,
                                          bool doRope, float prescale) {
    extern __shared__ char gsc[];
    const uint32_t sbase = smem_u32(gsc);
    const int tid  = threadIdx.x;
    const int lane = tid & 31;
    const int wid  = tid >> 5;      // 0..7
    const int wm   = wid & 1;       // 64 rows each
    const int wn   = wid >> 1;      // 32 cols each (0..3)
    const int m0   = blockIdx.y * 128;
    const int n0   = blockIdx.x * 128;

    float c[4][4][4];
#pragma unroll
    for (int mi = 0; mi < 4; mi++)
#pragma unroll
        for (int ni = 0; ni < 4; ni++)
#pragma unroll
            for (int j = 0; j < 4; j++) c[mi][ni][j] = 0.f;

    auto stage = [&](int kt, int slot) {
        const uint32_t base = sbase + slot * GSTAGE_B;
#pragma unroll
        for (int i = 0; i < 4; i++) {
            int cidx = tid + i * 256;
            int row = cidx >> 3, ch = cidx & 7;
            uint32_t off = (uint32_t)row * 128 + ((ch ^ (row & 7)) << 4);
            CP_ASYNC16(base + off,
                       Ag + (size_t)(m0 + row) * Kdim + kt * 64 + ch * 8);
            CP_ASYNC16(base + GTILE_B + off,
                       Bg + (size_t)(n0 + row) * Kdim + kt * 64 + ch * 8);
        }
    };

    const int a_row = wm * 64 + (lane & 15);
    const int a_hi  = lane >> 4;
    const int b_row = wn * 32 + (lane & 7) + ((lane >> 4) << 3);
    const int b_hi  = (lane >> 3) & 1;

    stage(0, 0); CP_COMMIT();
    stage(1, 1); CP_COMMIT();

    constexpr int NKT = Kdim / 64;   // 32
    int slot = 0;
    for (int kt = 0; kt < NKT; kt++) {
        CP_WAIT(1);
        __syncthreads();
        if (kt + 2 < NKT) {
            int ns = slot + 2; if (ns >= 3) ns -= 3;
            stage(kt + 2, ns);
        }
        CP_COMMIT();

        const uint32_t abase = sbase + slot * GSTAGE_B;
        const uint32_t bbase = abase + GTILE_B;
#pragma unroll
        for (int ks = 0; ks < 4; ks++) {   // k16 steps
            uint32_t af[4][4];
#pragma unroll
            for (int mi = 0; mi < 4; mi++) {
                int row = a_row + mi * 16;
                uint32_t addr = abase + (uint32_t)row * 128
                              + (((ks * 2 + a_hi) ^ (row & 7)) << 4);
                ldsm_x4(af[mi], addr);
            }
#pragma unroll
            for (int nip = 0; nip < 2; nip++) {
                int row = b_row + nip * 16;
                uint32_t addr = bbase + (uint32_t)row * 128
                              + (((ks * 2 + b_hi) ^ (row & 7)) << 4);
                uint32_t bf[4];
                ldsm_x4(bf, addr);
#pragma unroll
                for (int mi = 0; mi < 4; mi++) {
                    mma_f16(c[mi][2 * nip],     af[mi], bf[0], bf[1]);
                    mma_f16(c[mi][2 * nip + 1], af[mi], bf[2], bf[3]);
                }
            }
        }
        slot++; if (slot >= 3) slot = 0;
    }

    const int gid = lane >> 2, tig = lane & 3;
#pragma unroll
    for (int mi = 0; mi < 4; mi++) {
#pragma unroll
        for (int ni = 0; ni < 4; ni++) {
            int n = n0 + wn * 32 + ni * 8 + tig * 2;
#pragma unroll
            for (int half2i = 0; half2i < 2; half2i++) {
                int m = m0 + wm * 64 + mi * 16 + gid + half2i * 8;
                float2 v = make_float2(c[mi][ni][half2i * 2],
                                       c[mi][ni][half2i * 2 + 1]);
                if (OUTMODE == 0) {
                    *(float2*)((float*)Cg + (size_t)m * 2048 + n) = v;
                } else {
                    if (doRope) {
                        int pi   = (n & 127) >> 1;
                        int npos = m & 2047;
                        float2 sc = g_rope[(npos << 6) + pi];
                        float ev = v.x * sc.y - v.y * sc.x;
                        float ov = v.y * sc.y + v.x * sc.x;
                        v = make_float2(ev, ov);
                    }
                    v.x *= prescale; v.y *= prescale;
                    int b2 = m >> 11, np = m & 2047, h2 = n >> 7, a0 = n & 127;
                    if (OUTMODE == 2) {
                        __half* p = (__half*)Cg
                                  + (((size_t)b2 * H + h2) * A + a0) * N + np;
                        p[0] = __float2half_rn(v.x);
                        p[N] = __float2half_rn(v.y);
                    } else {
                        uint32_t pk = pack_f16x2(v.x, v.y);
                        *(uint32_t*)((__half*)Cg
                            + ((((size_t)b2 * H + h2) * N) + np) * A + a0) = pk;
                    }
                }
            }
        }
    }
}

// Q/K/V fused projections. z=0: Q (rope + scale*log2e), z=1: K (rope),
// z=2: V (transposed store).
__global__ __launch_bounds__(256, 2)
void qkv_gemm(const __half* __restrict__ q,
              const __half* __restrict__ Wq, const __half* __restrict__ Wk,
              const __half* __restrict__ Wv,
              __half* __restrict__ Qp, __half* __restrict__ Kp,
              __half* __restrict__ VTp) {
    const int z = blockIdx.z;
    const float QSCL = 0.08838834764831845f * 1.4426950408889634f;
    if (z == 0)      gemm_body<1>(q, Wq, Qp,  true,  QSCL);
    else if (z == 1) gemm_body<1>(q, Wk, Kp,  true,  1.0f);
    else             gemm_body<2>(q, Wv, VTp, false, 1.0f);
}

__global__ __launch_bounds__(256, 2)
void out_gemm(const __half* __restrict__ Ag, const __half* __restrict__ Bg,
              float* __restrict__ Cg) {
    gemm_body<0>(Ag, Bg, Cg, false, 1.0f);
}

// ---------------------------------------------------------------------------
// fp16 tensor-core causal flash attention v9.
// CTA: 128 queries, 256 threads (8 warps x 16 q rows), 64-key tiles, 3-stage.
// Staging bytes per query HALVED vs the 64q version (same 32KB tile serves
// 2x the queries). Per-warp causal tail: nktw = 2qt + 1 + (wid>>2).
// ---------------------------------------------------------------------------
constexpr int AQT = 128;
constexpr int AKT = 64;
constexpr int K_TILE_B   = AKT * 256;              // 16384 (64 rows x 256B)
constexpr int V_TILE_B   = 128 * 128;              // 16384 (128 rows x 128B)
constexpr int ASTAGE_B   = K_TILE_B + V_TILE_B;    // 32768
constexpr int ATTN_SMEM  = 3 * ASTAGE_B;           // 98304

__global__ __launch_bounds__(256, 1)
void attn_mma_kernel(const __half* __restrict__ Q, const __half* __restrict__ K,
                     const __half* __restrict__ VT, __half* __restrict__ O) {
    extern __shared__ char smc[];
    const uint32_t sbase = smem_u32(smc);

    const int tid  = threadIdx.x;
    const int lane = tid & 31;
    const int wid  = tid >> 5;          // 0..7
    const int gid  = lane >> 2, tig = lane & 3;
    const int bh   = blockIdx.y;
    const int qt   = gridDim.x - 1 - blockIdx.x;   // heavy tiles first
    const int q0   = qt * AQT;

    const __half* Qb  = Q  + (size_t)bh * N * A;
    const __half* Kb  = K  + (size_t)bh * N * A;
    const __half* VTb = VT + (size_t)bh * A * N;

    // ---- stage Q (128 rows x 256B = 32KB) into stage-0 alias ----
    {
#pragma unroll
        for (int i = 0; i < 8; i++) {
            int cidx = tid + i * 256;          // 0..2047
            int row = cidx >> 4, ch = cidx & 15;
            uint32_t off = (uint32_t)row * 256 + ((ch ^ (row & 7)) << 4);
            CP_ASYNC16(sbase + off, Qb + (size_t)(q0 + row) * A + ch * 8);
        }
        CP_COMMIT();
        CP_WAIT(0);
        __syncthreads();
    }

    // ---- Q A-frags -> registers (already scaled in projection) ----
    uint32_t qf[8][4];
    {
        const int a_row = wid * 16 + (lane & 15);
        const int a_hi  = lane >> 4;
#pragma unroll
        for (int kd = 0; kd < 8; kd++) {
            uint32_t addr = sbase + (uint32_t)a_row * 256
                          + (((kd * 2 + a_hi) ^ (a_row & 7)) << 4);
            ldsm_x4(qf[kd], addr);
        }
    }
    __syncthreads();   // Q smem now reusable as KV stage 0

    // ---- KV staging (256 threads: 4+4 chunks each) ----
    auto stage = [&](int kt, int slot) {
        const uint32_t kb = sbase + slot * ASTAGE_B;
        const uint32_t vb = kb + K_TILE_B;
        const __half* Kg  = Kb  + (size_t)(kt * AKT) * A;
        const __half* VTg = VTb + (size_t)(kt * AKT);
#pragma unroll
        for (int i = 0; i < 4; i++) {
            int cidx = tid + i * 256;
            int row = cidx >> 4, ch = cidx & 15;
            uint32_t off = (uint32_t)row * 256 + ((ch ^ (row & 7)) << 4);
            CP_ASYNC16(kb + off, Kg + (size_t)row * A + ch * 8);
        }
#pragma unroll
        for (int i = 0; i < 4; i++) {
            int cidx = tid + i * 256;
            int row = cidx >> 3, ch = cidx & 7;   // d row, key chunk
            uint32_t off = (uint32_t)row * 128 + ((ch ^ (row & 7)) << 4);
            CP_ASYNC16(vb + off, VTg + (size_t)row * N + ch * 8);
        }
    };

    const int nkt  = 2 * qt + 2;                   // CTA-wide 64-key tiles
    const int nktw = 2 * qt + 1 + (wid >> 2);      // this warp's tiles

    float o[16][4];
#pragma unroll
    for (int nf = 0; nf < 16; nf++)
#pragma unroll
        for (int j = 0; j < 4; j++) o[nf][j] = 0.f;
    float m0 = -1e30f, m1 = -1e30f, l0 = 0.f, l1 = 0.f;

    const int row0 = q0 + wid * 16 + gid;
    const int row1 = row0 + 8;
    const int b_row = (lane & 7) + ((lane >> 4) << 3);   // 0..15
    const int b_hi  = (lane >> 3) & 1;

    stage(0, 0); CP_COMMIT();
    if (nkt > 1) { stage(1, 1); } CP_COMMIT();

    int slot = 0;
    for (int kt = 0; kt < nkt; kt++) {
        CP_WAIT(1);
        __syncthreads();
        if (kt + 2 < nkt) {
            int ns = slot + 2; if (ns >= 3) ns -= 3;
            stage(kt + 2, ns);
        }
        CP_COMMIT();

        if (kt < nktw) {
            const uint32_t kbase = sbase + slot * ASTAGE_B;
            const uint32_t vbase = kbase + K_TILE_B;

            // ---- S = Q K^T (64 keys = 8 n-groups) ----
            float s[8][4];
#pragma unroll
            for (int nk = 0; nk < 8; nk++)
#pragma unroll
                for (int j = 0; j < 4; j++) s[nk][j] = 0.f;

#pragma unroll
            for (int kd = 0; kd < 8; kd++) {
#pragma unroll
                for (int g = 0; g < 4; g++) {
                    int row = b_row + g * 16;
                    uint32_t addr = kbase + (uint32_t)row * 256
                                  + (((kd * 2 + b_hi) ^ (row & 7)) << 4);
                    uint32_t bf[4];
                    ldsm_x4(bf, addr);
                    mma_f16(s[2 * g],     qf[kd], bf[0], bf[1]);
                    mma_f16(s[2 * g + 1], qf[kd], bf[2], bf[3]);
                }
            }

            // ---- causal mask (this warp's diagonal tile only) ----
            if (kt == nktw - 1) {
                int colb = kt * AKT + 2 * tig;
#pragma unroll
                for (int nk = 0; nk < 8; nk++) {
                    int c0 = colb + nk * 8;
                    if (c0     > row0) s[nk][0] = -1e30f;
                    if (c0 + 1 > row0) s[nk][1] = -1e30f;
                    if (c0     > row1) s[nk][2] = -1e30f;
                    if (c0 + 1 > row1) s[nk][3] = -1e30f;
                }
            }

            // ---- online softmax (log2 domain) ----
            float mx0 = -1e30f, mx1 = -1e30f;
#pragma unroll
            for (int nk = 0; nk < 8; nk++) {
                mx0 = fmaxf(mx0, fmaxf(s[nk][0], s[nk][1]));
                mx1 = fmaxf(mx1, fmaxf(s[nk][2], s[nk][3]));
            }
            mx0 = fmaxf(mx0, __shfl_xor_sync(0xffffffffu, mx0, 1));
            mx0 = fmaxf(mx0, __shfl_xor_sync(0xffffffffu, mx0, 2));
            mx1 = fmaxf(mx1, __shfl_xor_sync(0xffffffffu, mx1, 1));
            mx1 = fmaxf(mx1, __shfl_xor_sync(0xffffffffu, mx1, 2));
            float mn0 = fmaxf(m0, mx0), mn1 = fmaxf(m1, mx1);
            float cor0 = ex2f(m0 - mn0), cor1 = ex2f(m1 - mn1);
            m0 = mn0; m1 = mn1;

            float rs0 = 0.f, rs1 = 0.f;
#pragma unroll
            for (int nk = 0; nk < 8; nk++) {
                s[nk][0] = ex2f(s[nk][0] - mn0);
                s[nk][1] = ex2f(s[nk][1] - mn0);
                s[nk][2] = ex2f(s[nk][2] - mn1);
                s[nk][3] = ex2f(s[nk][3] - mn1);
                rs0 += s[nk][0] + s[nk][1];
                rs1 += s[nk][2] + s[nk][3];
            }
            rs0 += __shfl_xor_sync(0xffffffffu, rs0, 1);
            rs0 += __shfl_xor_sync(0xffffffffu, rs0, 2);
            rs1 += __shfl_xor_sync(0xffffffffu, rs1, 1);
            rs1 += __shfl_xor_sync(0xffffffffu, rs1, 2);
            l0 = l0 * cor0 + rs0;
            l1 = l1 * cor1 + rs1;

#pragma unroll
            for (int nf = 0; nf < 16; nf++) {
                o[nf][0] *= cor0; o[nf][1] *= cor0;
                o[nf][2] *= cor1; o[nf][3] *= cor1;
            }

            // ---- P A-frags: fp16x2 packs of S C-frags ----
            uint32_t aP[4][4];
#pragma unroll
            for (int kf = 0; kf < 4; kf++) {
                aP[kf][0] = pack_f16x2(s[2 * kf][0],     s[2 * kf][1]);
                aP[kf][1] = pack_f16x2(s[2 * kf][2],     s[2 * kf][3]);
                aP[kf][2] = pack_f16x2(s[2 * kf + 1][0], s[2 * kf + 1][1]);
                aP[kf][3] = pack_f16x2(s[2 * kf + 1][2], s[2 * kf + 1][3]);
            }

            // ---- O += P V : ldmatrix B-frags from d-major Vt tile ----
#pragma unroll
            for (int kf = 0; kf < 4; kf++) {
#pragma unroll
                for (int dp = 0; dp < 8; dp++) {
                    int row = dp * 16 + b_row;   // d row 0..127
                    uint32_t addr = vbase + (uint32_t)row * 128
                                  + (((kf * 2 + b_hi) ^ (row & 7)) << 4);
                    uint32_t bf[4];
                    ldsm_x4(bf, addr);
                    mma_f16(o[2 * dp],     aP[kf], bf[0], bf[1]);
                    mma_f16(o[2 * dp + 1], aP[kf], bf[2], bf[3]);
                }
            }
        }

        slot++; if (slot >= 3) slot = 0;
    }

    // ---- write output: fp16 [b*n, h*a] ----
    const float il0 = 1.f / l0, il1 = 1.f / l1;
    const int b2 = bh >> 4, h2 = bh & 15;
    __half* o0 = O + (size_t)(b2 * N + row0) * HD + h2 * A;
    __half* o1 = O + (size_t)(b2 * N + row1) * HD + h2 * A;
#pragma unroll
    for (int nf = 0; nf < 16; nf++) {
        int col = nf * 8 + 2 * tig;
        *(uint32_t*)(o0 + col) = pack_f16x2(o[nf][0] * il0, o[nf][1] * il0);
        *(uint32_t*)(o1 + col) = pack_f16x2(o[nf][2] * il1, o[nf][3] * il1);
    }
}

// ---------------------------------------------------------------------------
extern "C" void kernel_launch(void* const* d_in, const int* in_sizes, int n_in,
                              void* d_out, int out_size) {
    const float* q  = (const float*)d_in[0];
    const float* Wq = (const float*)d_in[1];
    const float* Wk = (const float*)d_in[2];
    const float* Wv = (const float*)d_in[3];
    const float* Wo = (const float*)d_in[4];
    float* out = (float*)d_out;

    __half *qh, *Wqh, *Wkh, *Wvh, *Woh, *Qh, *Kh, *VTh, *AOh;
    cudaGetSymbolAddress((void**)&qh,  g_qh);
    cudaGetSymbolAddress((void**)&Wqh, g_Wqh);
    cudaGetSymbolAddress((void**)&Wkh, g_Wkh);
    cudaGetSymbolAddress((void**)&Wvh, g_Wvh);
    cudaGetSymbolAddress((void**)&Woh, g_Woh);
    cudaGetSymbolAddress((void**)&Qh,  g_Qh);
    cudaGetSymbolAddress((void**)&Kh,  g_Kh);
    cudaGetSymbolAddress((void**)&VTh, g_VTh);
    cudaGetSymbolAddress((void**)&AOh, g_AOh);

    cudaFuncSetAttribute(qkv_gemm, cudaFuncAttributeMaxDynamicSharedMemorySize,
                         GEMM_SMEM);
    cudaFuncSetAttribute(out_gemm, cudaFuncAttributeMaxDynamicSharedMemorySize,
                         GEMM_SMEM);
    cudaFuncSetAttribute(attn_mma_kernel,
                         cudaFuncAttributeMaxDynamicSharedMemorySize, ATTN_SMEM);

    // fused fp16 conversion + rope table (single launch)
    {
        int total = NTOT4 + NROPE;   // 6,422,528
        cvt_all_kernel<<<(total + 255) / 256, 256>>>(
            (const float4*)q, (const float4*)Wq, (const float4*)Wk,
            (const float4*)Wv, (const float4*)Wo,
            qh, Wqh, Wkh, Wvh, Woh);
    }

    // fused QKV projections (rope + scale fused; V stored transposed)
    qkv_gemm<<<dim3(16, 32, 3), 256, GEMM_SMEM>>>(qh, Wqh, Wkh, Wvh, Qh, Kh, VTh);

    // fp16 tensor-core causal flash attention (128q CTAs, 64-key tiles)
    attn_mma_kernel<<<dim3(N / AQT, B * H), 256, ATTN_SMEM>>>(Qh, Kh, VTh, AOh);

    // output projection (fp32 result)
    out_gemm<<<dim3(16, 32), 256, GEMM_SMEM>>>(AOh, Woh, out);
}